// round 1
// baseline (speedup 1.0000x reference)
#include <cuda_runtime.h>

// Problem dims (fixed by setup_inputs): adj [2048,2048], x [2,8,2048,128],
// weight [128,128], bias [128]. Output [2,8,2048,128] float32.
#define NN    2048
#define ABATCH 16          // A*B = 2*8
#define DIN   128
#define DOUT  128
#define ROWCHUNKS 16       // partial-sum chunks for colsum (2048/16 = 128 rows each)

// -------- device scratch (no allocations allowed) --------
__device__ float g_part[ROWCHUNKS * NN];      // partial column sums
__device__ float g_rinv[NN];                  // rsqrt(colsum)
__device__ float g_y[ABATCH * NN * DOUT];     // rinv-scaled projected features (16 MB)

// ============================================================
// Kernel 1: partial column sums of adj (deterministic, no atomics)
// grid (NN/256, ROWCHUNKS), block 256
// ============================================================
__global__ void colsum_part_kernel(const float* __restrict__ adj) {
    int col = blockIdx.x * 256 + threadIdx.x;
    int r0  = blockIdx.y * (NN / ROWCHUNKS);
    float s = 0.f;
#pragma unroll 4
    for (int r = 0; r < NN / ROWCHUNKS; ++r)
        s += adj[(size_t)(r0 + r) * NN + col];
    g_part[blockIdx.y * NN + col] = s;
}

// ============================================================
// Kernel 2: reduce partials -> rinv = rsqrt(colsum)
// grid NN/256, block 256
// ============================================================
__global__ void rinv_kernel() {
    int col = blockIdx.x * 256 + threadIdx.x;
    float s = 0.f;
#pragma unroll
    for (int c = 0; c < ROWCHUNKS; ++c)
        s += g_part[c * NN + col];
    g_rinv[col] = rsqrtf(s);
}

// ============================================================
// Kernel 3: projection  y[row, d] = rinv[row % NN] * sum_k x[row,k] * W[k,d]
// rows = ABATCH*NN = 32768. Tile BM=64, BN=128, BK=16. 256 threads,
// per-thread 4x8 microtile. grid = 32768/64 = 512 blocks.
// ============================================================
__global__ void project_kernel(const float* __restrict__ x,
                               const float* __restrict__ w) {
    __shared__ float Xs[16][64];    // [k][m]
    __shared__ float Ws[16][128];   // [k][n]

    const int m0  = blockIdx.x * 64;
    const int tid = threadIdx.x;

    // A-tile load mapping: one float4 per thread per K-step
    const int lr = tid >> 2;            // 0..63 row within tile
    const int lk = (tid & 3) * 4;       // 0,4,8,12 k-offset

    const int ty = tid >> 4;            // 0..15 -> m microtile
    const int tx = tid & 15;            // 0..15 -> n microtile

    float acc[4][8];
#pragma unroll
    for (int i = 0; i < 4; ++i)
#pragma unroll
        for (int j = 0; j < 8; ++j) acc[i][j] = 0.f;

    for (int k0 = 0; k0 < DIN; k0 += 16) {
        // load X tile (64x16), transposed into Xs[k][m]
        float4 av = *(const float4*)&x[(size_t)(m0 + lr) * DIN + k0 + lk];
        Xs[lk + 0][lr] = av.x;
        Xs[lk + 1][lr] = av.y;
        Xs[lk + 2][lr] = av.z;
        Xs[lk + 3][lr] = av.w;
        // load W tile (16x128): 512 float4, 2 per thread
#pragma unroll
        for (int i = 0; i < 2; ++i) {
            int idx = tid + i * 256;        // 0..511
            int kr  = idx >> 5;             // /32 f4 per row
            int nc  = (idx & 31) << 2;
            *(float4*)&Ws[kr][nc] = *(const float4*)&w[(size_t)(k0 + kr) * DOUT + nc];
        }
        __syncthreads();

#pragma unroll
        for (int k = 0; k < 16; ++k) {
            float a[4], b[8];
#pragma unroll
            for (int i = 0; i < 4; ++i) a[i] = Xs[k][ty * 4 + i];
            *(float4*)&b[0] = *(float4*)&Ws[k][tx * 8];
            *(float4*)&b[4] = *(float4*)&Ws[k][tx * 8 + 4];
#pragma unroll
            for (int i = 0; i < 4; ++i)
#pragma unroll
                for (int j = 0; j < 8; ++j)
                    acc[i][j] = fmaf(a[i], b[j], acc[i][j]);
        }
        __syncthreads();
    }

    // epilogue: scale by rinv[n] (n = global row mod NN; tiles never straddle ab)
#pragma unroll
    for (int i = 0; i < 4; ++i) {
        int row = m0 + ty * 4 + i;
        float rv = g_rinv[row & (NN - 1)];
        float4 v0 = make_float4(acc[i][0] * rv, acc[i][1] * rv, acc[i][2] * rv, acc[i][3] * rv);
        float4 v1 = make_float4(acc[i][4] * rv, acc[i][5] * rv, acc[i][6] * rv, acc[i][7] * rv);
        *(float4*)&g_y[(size_t)row * DOUT + tx * 8]     = v0;
        *(float4*)&g_y[(size_t)row * DOUT + tx * 8 + 4] = v1;
    }
}

// ============================================================
// Kernel 4: aggregation
//   out[ab, m, d] = relu( rinv[m] * sum_n adj[n, m] * y[ab, n, d] + bias[d] )
// C = adj^T (KxM, K-major) @ y_ab (KxN, K-major). BM=128, BN=128, BK=16.
// 256 threads, 8x8 microtiles. grid = (16 m-tiles, 16 ab).
// ============================================================
__global__ void aggregate_kernel(const float* __restrict__ adj,
                                 const float* __restrict__ bias,
                                 float* __restrict__ out) {
    __shared__ float As[16][128];   // adj[n][m] tile, [k][m]
    __shared__ float Bs[16][128];   // y[n][d]  tile, [k][n]

    const int m0 = blockIdx.x * 128;
    const int ab = blockIdx.y;
    const float* __restrict__ y = g_y + (size_t)ab * NN * DOUT;

    const int tid = threadIdx.x;
    const int ty  = tid >> 4;       // 0..15 -> m
    const int tx  = tid & 15;       // 0..15 -> d

    float acc[8][8];
#pragma unroll
    for (int i = 0; i < 8; ++i)
#pragma unroll
        for (int j = 0; j < 8; ++j) acc[i][j] = 0.f;

    for (int n0 = 0; n0 < NN; n0 += 16) {
        // each tile: 16x128 = 512 float4 total, 2 per thread
#pragma unroll
        for (int i = 0; i < 2; ++i) {
            int idx = tid + i * 256;        // 0..511
            int kr  = idx >> 5;
            int mc  = (idx & 31) << 2;
            *(float4*)&As[kr][mc] = *(const float4*)&adj[(size_t)(n0 + kr) * NN + m0 + mc];
            *(float4*)&Bs[kr][mc] = *(const float4*)&y[(size_t)(n0 + kr) * DOUT + mc];
        }
        __syncthreads();

#pragma unroll
        for (int k = 0; k < 16; ++k) {
            float a[8], b[8];
            *(float4*)&a[0] = *(float4*)&As[k][ty * 8];
            *(float4*)&a[4] = *(float4*)&As[k][ty * 8 + 4];
            *(float4*)&b[0] = *(float4*)&Bs[k][tx * 8];
            *(float4*)&b[4] = *(float4*)&Bs[k][tx * 8 + 4];
#pragma unroll
            for (int i = 0; i < 8; ++i)
#pragma unroll
                for (int j = 0; j < 8; ++j)
                    acc[i][j] = fmaf(a[i], b[j], acc[i][j]);
        }
        __syncthreads();
    }

    // epilogue: rinv[m] scale, +bias, relu
    float bvals[8];
    *(float4*)&bvals[0] = *(const float4*)&bias[tx * 8];
    *(float4*)&bvals[4] = *(const float4*)&bias[tx * 8 + 4];

    float* outab = out + (size_t)ab * NN * DOUT;
#pragma unroll
    for (int i = 0; i < 8; ++i) {
        int m = m0 + ty * 8 + i;
        float rv = g_rinv[m];
        float4 v0, v1;
        v0.x = fmaxf(fmaf(acc[i][0], rv, bvals[0]), 0.f);
        v0.y = fmaxf(fmaf(acc[i][1], rv, bvals[1]), 0.f);
        v0.z = fmaxf(fmaf(acc[i][2], rv, bvals[2]), 0.f);
        v0.w = fmaxf(fmaf(acc[i][3], rv, bvals[3]), 0.f);
        v1.x = fmaxf(fmaf(acc[i][4], rv, bvals[4]), 0.f);
        v1.y = fmaxf(fmaf(acc[i][5], rv, bvals[5]), 0.f);
        v1.z = fmaxf(fmaf(acc[i][6], rv, bvals[6]), 0.f);
        v1.w = fmaxf(fmaf(acc[i][7], rv, bvals[7]), 0.f);
        *(float4*)&outab[(size_t)m * DOUT + tx * 8]     = v0;
        *(float4*)&outab[(size_t)m * DOUT + tx * 8 + 4] = v1;
    }
}

// ============================================================
extern "C" void kernel_launch(void* const* d_in, const int* in_sizes, int n_in,
                              void* d_out, int out_size) {
    const float* adj  = (const float*)d_in[0];   // [2048, 2048]
    const float* x    = (const float*)d_in[1];   // [2, 8, 2048, 128]
    const float* w    = (const float*)d_in[2];   // [128, 128]
    const float* bias = (const float*)d_in[3];   // [128]
    float* out        = (float*)d_out;           // [2, 8, 2048, 128]

    colsum_part_kernel<<<dim3(NN / 256, ROWCHUNKS), 256>>>(adj);
    rinv_kernel<<<NN / 256, 256>>>();
    project_kernel<<<(ABATCH * NN) / 64, 256>>>(x, w);
    aggregate_kernel<<<dim3(NN / 128, ABATCH), 256>>>(adj, bias, out);
}

// round 4
// speedup vs baseline: 3.6725x; 3.6725x over previous
#include <cuda_runtime.h>
#include <cuda_bf16.h>
#include <cstdint>

// dims fixed by setup_inputs
#define NN     2048
#define ABATCH 16
#define DIN    128
#define DOUT   128
#define TCHUNKS 64

// ---------------- device scratch (no allocs allowed) ----------------
__device__ float g_part[TCHUNKS * NN];
__device__ float g_rinv[NN];
__device__ __nv_bfloat16 g_adjT[(size_t)NN * NN];           // adjT[m][n] = adj[n][m], 8 MB
__device__ __nv_bfloat16 g_yT[(size_t)ABATCH * DOUT * NN];  // yT[ab][d][n], 8 MB

__device__ __forceinline__ uint32_t smem_u32(const void* p) {
    return (uint32_t)__cvta_generic_to_shared(p);
}
__device__ __forceinline__ void cp_async16(uint32_t dst, const void* src) {
    asm volatile("cp.async.cg.shared.global [%0], [%1], 16;" :: "r"(dst), "l"(src));
}
__device__ __forceinline__ void cp_commit() {
    asm volatile("cp.async.commit_group;" ::: "memory");
}
template <int N>
__device__ __forceinline__ void cp_wait() {
    asm volatile("cp.async.wait_group %0;" :: "n"(N) : "memory");
}
__device__ __forceinline__ void ldsm_x4(uint32_t* r, uint32_t addr) {
    asm volatile("ldmatrix.sync.aligned.m8n8.x4.shared.b16 {%0,%1,%2,%3}, [%4];"
                 : "=r"(r[0]), "=r"(r[1]), "=r"(r[2]), "=r"(r[3]) : "r"(addr));
}
__device__ __forceinline__ void mma16816(float* d, const uint32_t* a, const uint32_t* b) {
    asm volatile(
        "mma.sync.aligned.m16n8k16.row.col.f32.bf16.bf16.f32 "
        "{%0,%1,%2,%3}, {%4,%5,%6,%7}, {%8,%9}, {%0,%1,%2,%3};"
        : "+f"(d[0]), "+f"(d[1]), "+f"(d[2]), "+f"(d[3])
        : "r"(a[0]), "r"(a[1]), "r"(a[2]), "r"(a[3]), "r"(b[0]), "r"(b[1]));
}
__device__ __forceinline__ uint32_t pack_bf2(float a, float b) {
    __nv_bfloat162 t = __floats2bfloat162_rn(a, b);
    return *(uint32_t*)&t;
}

// ============================================================
// Kernel 1: fused transpose + partial column sums
// grid (64 m-tiles, 64 n-tiles), block (32, 8)
// ============================================================
__global__ void transpose_colsum_kernel(const float* __restrict__ adj) {
    __shared__ float t[32][33];
    int mx = blockIdx.x * 32, ny = blockIdx.y * 32;
    int tx = threadIdx.x, ty = threadIdx.y;
    float v[4];
#pragma unroll
    for (int i = 0; i < 4; ++i) {
        v[i] = adj[(size_t)(ny + ty + i * 8) * NN + mx + tx];
        t[ty + i * 8][tx] = v[i];
    }
    __syncthreads();
#pragma unroll
    for (int i = 0; i < 4; ++i)
        g_adjT[(size_t)(mx + ty + i * 8) * NN + ny + tx] = __float2bfloat16(t[tx][ty + i * 8]);
    float s = v[0] + v[1] + v[2] + v[3];
    __syncthreads();
    t[ty][tx] = s;
    __syncthreads();
    if (ty == 0) {
        float tot = 0.f;
#pragma unroll
        for (int r = 0; r < 8; ++r) tot += t[r][tx];
        g_part[blockIdx.y * NN + mx + tx] = tot;
    }
}

// ============================================================
// Kernel 2: reduce -> rinv = rsqrt(colsum)
// ============================================================
__global__ void rinv_kernel() {
    int col = blockIdx.x * 256 + threadIdx.x;
    float s = 0.f;
#pragma unroll
    for (int c = 0; c < TCHUNKS; ++c)
        s += g_part[c * NN + col];
    g_rinv[col] = rsqrtf(s);
}

// ============================================================
// Kernel 3: projection (fp32) -> transposed bf16 output
//   yT[ab][d][n] = bf16( rinv[n] * sum_k x[ab,n,k] * W[k,d] )
// grid = (16 n-tiles, 16 ab), 256 threads, 8x8 microtiles
// ============================================================
__global__ void __launch_bounds__(256) project_kernel(const float* __restrict__ x,
                                                      const float* __restrict__ w) {
    __shared__ float Ws[16][128];
    __shared__ float Xs[16][128];

    const int n0 = blockIdx.x * 128;
    const int ab = blockIdx.y;
    const float* __restrict__ xab = x + (size_t)ab * NN * DIN;

    const int tid = threadIdx.x;
    const int ty  = tid >> 4;
    const int tx  = tid & 15;

    float acc[8][8];
#pragma unroll
    for (int i = 0; i < 8; ++i)
#pragma unroll
        for (int j = 0; j < 8; ++j) acc[i][j] = 0.f;

    for (int k0 = 0; k0 < DIN; k0 += 16) {
#pragma unroll
        for (int i = 0; i < 2; ++i) {
            int idx = tid + i * 256;
            int kr  = idx >> 5;
            int dc  = (idx & 31) << 2;
            *(float4*)&Ws[kr][dc] = *(const float4*)&w[(size_t)(k0 + kr) * DOUT + dc];
        }
#pragma unroll
        for (int i = 0; i < 2; ++i) {
            int idx = tid + i * 256;
            int nr  = idx >> 2;
            int kc  = (idx & 3) << 2;
            float4 v = *(const float4*)&xab[(size_t)(n0 + nr) * DIN + k0 + kc];
            Xs[kc + 0][nr] = v.x;
            Xs[kc + 1][nr] = v.y;
            Xs[kc + 2][nr] = v.z;
            Xs[kc + 3][nr] = v.w;
        }
        __syncthreads();

#pragma unroll
        for (int k = 0; k < 16; ++k) {
            float a[8], b[8];
            *(float4*)&a[0] = *(float4*)&Ws[k][ty * 8];
            *(float4*)&a[4] = *(float4*)&Ws[k][ty * 8 + 4];
            *(float4*)&b[0] = *(float4*)&Xs[k][tx * 8];
            *(float4*)&b[4] = *(float4*)&Xs[k][tx * 8 + 4];
#pragma unroll
            for (int i = 0; i < 8; ++i)
#pragma unroll
                for (int j = 0; j < 8; ++j)
                    acc[i][j] = fmaf(a[i], b[j], acc[i][j]);
        }
        __syncthreads();
    }

    float rv[8];
#pragma unroll
    for (int j = 0; j < 8; ++j) rv[j] = g_rinv[n0 + tx * 8 + j];

    __nv_bfloat16* yT = g_yT + (size_t)ab * DOUT * NN;
#pragma unroll
    for (int i = 0; i < 8; ++i) {
        int d = ty * 8 + i;
        uint4 pk;
        pk.x = pack_bf2(acc[i][0] * rv[0], acc[i][1] * rv[1]);
        pk.y = pack_bf2(acc[i][2] * rv[2], acc[i][3] * rv[3]);
        pk.z = pack_bf2(acc[i][4] * rv[4], acc[i][5] * rv[5]);
        pk.w = pack_bf2(acc[i][6] * rv[6], acc[i][7] * rv[7]);
        *(uint4*)((char*)yT + ((size_t)d * NN + n0 + tx * 8) * 2) = pk;
    }
}

// ============================================================
// Kernel 4: mma.sync bf16 aggregate
//   out[ab][m][d] = relu( rinv[m] * sum_n adjT[m][n]*yT[ab][d][n] + bias[d] )
// CTA tile 128m x 128d, BK=64, 8 warps (4 m x 2 d), warp tile 32x64.
// cp.async double-buffered; SW128 XOR swizzle; ldmatrix x4 for both operands
// (both are K-major -> plain ldmatrix, no .trans).
// grid (16 m-tiles, 16 ab), 256 threads.
// ============================================================
#define BK        64
#define ATILE_B   (128 * 128)     // 128 rows x 64 bf16 = 16 KB
#define BUF_B     (2 * ATILE_B)   // A + B per buffer = 32 KB
#define NCHUNKS   (NN / BK)       // 32

__global__ void __launch_bounds__(256, 1)
aggregate_mma(const float* __restrict__ bias, float* __restrict__ out) {
    extern __shared__ char smem_raw[];
    const uint32_t sbase = (smem_u32(smem_raw) + 127) & ~127u;

    const int tid  = threadIdx.x;
    const int wid  = tid >> 5;
    const int lane = tid & 31;
    const int warp_m = (wid & 3) * 32;    // 0,32,64,96
    const int warp_d = (wid >> 2) * 64;   // 0,64
    const int m0   = blockIdx.x * 128;
    const int ab   = blockIdx.y;

    const char* Ag = (const char*)(g_adjT + (size_t)m0 * NN);
    const char* Bg = (const char*)(g_yT + (size_t)ab * DOUT * NN);

    // loader mapping: 4 chunks each for A and B per buffer
    const int lrow = tid >> 1;                  // 0..127
    const int lc0  = (tid & 1) * 4;             // 0 or 4: this thread's 4 chunks

    auto load_buf = [&](int buf, int c) {
        const uint32_t Ao = sbase + buf * BUF_B;
        const uint32_t Bo = Ao + ATILE_B;
        const int n0 = c * BK;
        const size_t rowoff = (size_t)lrow * NN + n0;
#pragma unroll
        for (int i = 0; i < 4; ++i) {
            int ch = lc0 + i;
            uint32_t sw = (uint32_t)(ch ^ (lrow & 7)) * 16 + (uint32_t)lrow * 128;
            const size_t goff = (rowoff + ch * 8) * 2;
            cp_async16(Ao + sw, Ag + goff);
            cp_async16(Bo + sw, Bg + goff);
        }
        cp_commit();
    };

    float acc[2][8][4];
#pragma unroll
    for (int mf = 0; mf < 2; ++mf)
#pragma unroll
        for (int nf = 0; nf < 8; ++nf)
#pragma unroll
            for (int e = 0; e < 4; ++e) acc[mf][nf][e] = 0.f;

    load_buf(0, 0);

    const int portion = lane >> 3;
    const int w8 = lane & 7;

    for (int c = 0; c < NCHUNKS; ++c) {
        const int buf = c & 1;
        if (c + 1 < NCHUNKS) {
            load_buf(1 - buf, c + 1);
            cp_wait<1>();
        } else {
            cp_wait<0>();
        }
        __syncthreads();

        const uint32_t Ao = sbase + buf * BUF_B;
        const uint32_t Bo = Ao + ATILE_B;

#pragma unroll
        for (int ks = 0; ks < 4; ++ks) {
            const int kb8 = ks * 2;
            uint32_t a[2][4], b[8][2];
            // A: mats (m..+7,k0-7),(m+8..+15,k0-7),(m..+7,k8-15),(m+8..+15,k8-15)
#pragma unroll
            for (int mf = 0; mf < 2; ++mf) {
                int row = warp_m + mf * 16 + (portion & 1) * 8 + w8;
                int ch  = kb8 + (portion >> 1);
                ldsm_x4(a[mf], Ao + (uint32_t)row * 128 + (uint32_t)(ch ^ (row & 7)) * 16);
            }
            // B: per pair of n-frags: mats (d..+7,k0-7),(d..+7,k8-15),(d+8..+15,k0-7),(d+8..+15,k8-15)
#pragma unroll
            for (int nfp = 0; nfp < 4; ++nfp) {
                int row = warp_d + nfp * 16 + (portion >> 1) * 8 + w8;
                int ch  = kb8 + (portion & 1);
                uint32_t r[4];
                ldsm_x4(r, Bo + (uint32_t)row * 128 + (uint32_t)(ch ^ (row & 7)) * 16);
                b[2 * nfp][0]     = r[0];
                b[2 * nfp][1]     = r[1];
                b[2 * nfp + 1][0] = r[2];
                b[2 * nfp + 1][1] = r[3];
            }
#pragma unroll
            for (int mf = 0; mf < 2; ++mf)
#pragma unroll
                for (int nf = 0; nf < 8; ++nf)
                    mma16816(acc[mf][nf], a[mf], b[nf]);
        }
        __syncthreads();
    }

    // epilogue: rinv[m] * acc + bias[d], relu
    const int g  = lane >> 2;
    const int tc = lane & 3;
    float* outab = out + (size_t)ab * NN * DOUT;
#pragma unroll
    for (int mf = 0; mf < 2; ++mf) {
        const int mrow0 = m0 + warp_m + mf * 16 + g;
        const float rv0 = g_rinv[mrow0];
        const float rv1 = g_rinv[mrow0 + 8];
#pragma unroll
        for (int nf = 0; nf < 8; ++nf) {
            const int d0 = warp_d + nf * 8 + tc * 2;
            const float b0 = __ldg(&bias[d0]);
            const float b1 = __ldg(&bias[d0 + 1]);
            float2 v0, v1;
            v0.x = fmaxf(fmaf(acc[mf][nf][0], rv0, b0), 0.f);
            v0.y = fmaxf(fmaf(acc[mf][nf][1], rv0, b1), 0.f);
            v1.x = fmaxf(fmaf(acc[mf][nf][2], rv1, b0), 0.f);
            v1.y = fmaxf(fmaf(acc[mf][nf][3], rv1, b1), 0.f);
            *(float2*)&outab[(size_t)mrow0 * DOUT + d0]       = v0;
            *(float2*)&outab[(size_t)(mrow0 + 8) * DOUT + d0] = v1;
        }
    }
}

// ============================================================
extern "C" void kernel_launch(void* const* d_in, const int* in_sizes, int n_in,
                              void* d_out, int out_size) {
    const float* adj  = (const float*)d_in[0];
    const float* x    = (const float*)d_in[1];
    const float* w    = (const float*)d_in[2];
    const float* bias = (const float*)d_in[3];
    float* out        = (float*)d_out;

    const int agg_smem = 2 * BUF_B + 256;   // 64 KB + align slack
    cudaFuncSetAttribute(aggregate_mma, cudaFuncAttributeMaxDynamicSharedMemorySize, agg_smem);

    transpose_colsum_kernel<<<dim3(64, 64), dim3(32, 8)>>>(adj);
    rinv_kernel<<<NN / 256, 256>>>();
    project_kernel<<<dim3(16, 16), 256>>>(x, w);
    aggregate_mma<<<dim3(16, 16), 256, agg_smem>>>(bias, out);
}

// round 5
// speedup vs baseline: 4.1049x; 1.1177x over previous
#include <cuda_runtime.h>
#include <cuda_bf16.h>
#include <cstdint>

// dims fixed by setup_inputs
#define NN     2048
#define ABATCH 16
#define DIN    128
#define DOUT   128
#define TCHUNKS 64

// ---------------- device scratch (no allocs allowed) ----------------
__device__ float g_part[TCHUNKS * NN];
__device__ float g_rinv[NN];
__device__ __nv_bfloat16 g_adjT[(size_t)NN * NN];           // adjT[m][n] = adj[n][m], 8 MB
__device__ __nv_bfloat16 g_yT[(size_t)ABATCH * DOUT * NN];  // yT[ab][d][n], 8 MB

__device__ __forceinline__ uint32_t smem_u32(const void* p) {
    return (uint32_t)__cvta_generic_to_shared(p);
}
__device__ __forceinline__ void cp_async16(uint32_t dst, const void* src) {
    asm volatile("cp.async.cg.shared.global [%0], [%1], 16;" :: "r"(dst), "l"(src));
}
__device__ __forceinline__ void cp_commit() {
    asm volatile("cp.async.commit_group;" ::: "memory");
}
template <int N>
__device__ __forceinline__ void cp_wait() {
    asm volatile("cp.async.wait_group %0;" :: "n"(N) : "memory");
}
__device__ __forceinline__ void ldsm_x4(uint32_t* r, uint32_t addr) {
    asm volatile("ldmatrix.sync.aligned.m8n8.x4.shared.b16 {%0,%1,%2,%3}, [%4];"
                 : "=r"(r[0]), "=r"(r[1]), "=r"(r[2]), "=r"(r[3]) : "r"(addr));
}
__device__ __forceinline__ void mma16816(float* d, const uint32_t* a, const uint32_t* b) {
    asm volatile(
        "mma.sync.aligned.m16n8k16.row.col.f32.bf16.bf16.f32 "
        "{%0,%1,%2,%3}, {%4,%5,%6,%7}, {%8,%9}, {%0,%1,%2,%3};"
        : "+f"(d[0]), "+f"(d[1]), "+f"(d[2]), "+f"(d[3])
        : "r"(a[0]), "r"(a[1]), "r"(a[2]), "r"(a[3]), "r"(b[0]), "r"(b[1]));
}
__device__ __forceinline__ uint32_t pack_bf2(float a, float b) {
    __nv_bfloat162 t = __floats2bfloat162_rn(a, b);
    return *(uint32_t*)&t;
}

// ============================================================
// Kernel 1: fused transpose + partial column sums
// grid (64 m-tiles, 64 n-tiles), block (32, 8)
// ============================================================
__global__ void transpose_colsum_kernel(const float* __restrict__ adj) {
    __shared__ float t[32][33];
    int mx = blockIdx.x * 32, ny = blockIdx.y * 32;
    int tx = threadIdx.x, ty = threadIdx.y;
    float v[4];
#pragma unroll
    for (int i = 0; i < 4; ++i) {
        v[i] = adj[(size_t)(ny + ty + i * 8) * NN + mx + tx];
        t[ty + i * 8][tx] = v[i];
    }
    __syncthreads();
#pragma unroll
    for (int i = 0; i < 4; ++i)
        g_adjT[(size_t)(mx + ty + i * 8) * NN + ny + tx] = __float2bfloat16(t[tx][ty + i * 8]);
    float s = v[0] + v[1] + v[2] + v[3];
    __syncthreads();
    t[ty][tx] = s;
    __syncthreads();
    if (ty == 0) {
        float tot = 0.f;
#pragma unroll
        for (int r = 0; r < 8; ++r) tot += t[r][tx];
        g_part[blockIdx.y * NN + mx + tx] = tot;
    }
}

// ============================================================
// Kernel 2: reduce -> rinv = rsqrt(colsum)
// ============================================================
__global__ void rinv_kernel() {
    int col = blockIdx.x * 256 + threadIdx.x;
    float s = 0.f;
#pragma unroll
    for (int c = 0; c < TCHUNKS; ++c)
        s += g_part[c * NN + col];
    g_rinv[col] = rsqrtf(s);
}

// ============================================================
// Kernel 3: projection (fp32) -> transposed bf16 output
//   yT[ab][d][n] = bf16( rinv[n] * sum_k x[ab,n,k] * W[k,d] )
// grid = (16 n-tiles, 16 ab), 256 threads, 8x8 microtiles
// ============================================================
__global__ void __launch_bounds__(256) project_kernel(const float* __restrict__ x,
                                                      const float* __restrict__ w) {
    __shared__ float Ws[16][128];
    __shared__ float Xs[16][128];

    const int n0 = blockIdx.x * 128;
    const int ab = blockIdx.y;
    const float* __restrict__ xab = x + (size_t)ab * NN * DIN;

    const int tid = threadIdx.x;
    const int ty  = tid >> 4;
    const int tx  = tid & 15;

    float acc[8][8];
#pragma unroll
    for (int i = 0; i < 8; ++i)
#pragma unroll
        for (int j = 0; j < 8; ++j) acc[i][j] = 0.f;

    for (int k0 = 0; k0 < DIN; k0 += 16) {
#pragma unroll
        for (int i = 0; i < 2; ++i) {
            int idx = tid + i * 256;
            int kr  = idx >> 5;
            int dc  = (idx & 31) << 2;
            *(float4*)&Ws[kr][dc] = *(const float4*)&w[(size_t)(k0 + kr) * DOUT + dc];
        }
#pragma unroll
        for (int i = 0; i < 2; ++i) {
            int idx = tid + i * 256;
            int nr  = idx >> 2;
            int kc  = (idx & 3) << 2;
            float4 v = *(const float4*)&xab[(size_t)(n0 + nr) * DIN + k0 + kc];
            Xs[kc + 0][nr] = v.x;
            Xs[kc + 1][nr] = v.y;
            Xs[kc + 2][nr] = v.z;
            Xs[kc + 3][nr] = v.w;
        }
        __syncthreads();

#pragma unroll
        for (int k = 0; k < 16; ++k) {
            float a[8], b[8];
            *(float4*)&a[0] = *(float4*)&Ws[k][ty * 8];
            *(float4*)&a[4] = *(float4*)&Ws[k][ty * 8 + 4];
            *(float4*)&b[0] = *(float4*)&Xs[k][tx * 8];
            *(float4*)&b[4] = *(float4*)&Xs[k][tx * 8 + 4];
#pragma unroll
            for (int i = 0; i < 8; ++i)
#pragma unroll
                for (int j = 0; j < 8; ++j)
                    acc[i][j] = fmaf(a[i], b[j], acc[i][j]);
        }
        __syncthreads();
    }

    float rv[8];
#pragma unroll
    for (int j = 0; j < 8; ++j) rv[j] = g_rinv[n0 + tx * 8 + j];

    __nv_bfloat16* yT = g_yT + (size_t)ab * DOUT * NN;
#pragma unroll
    for (int i = 0; i < 8; ++i) {
        int d = ty * 8 + i;
        uint4 pk;
        pk.x = pack_bf2(acc[i][0] * rv[0], acc[i][1] * rv[1]);
        pk.y = pack_bf2(acc[i][2] * rv[2], acc[i][3] * rv[3]);
        pk.z = pack_bf2(acc[i][4] * rv[4], acc[i][5] * rv[5]);
        pk.w = pack_bf2(acc[i][6] * rv[6], acc[i][7] * rv[7]);
        *(uint4*)((char*)yT + ((size_t)d * NN + n0 + tx * 8) * 2) = pk;
    }
}

// ============================================================
// Kernel 4: mma.sync bf16 aggregate (v2: 512 threads, 3-stage pipeline)
//   out[ab][m][d] = relu( rinv[m] * sum_n adjT[m][n]*yT[ab][d][n] + bias[d] )
// CTA tile 128m x 128d, BK=64, 16 warps (4m x 4d), warp tile 32x32.
// 3-stage cp.async pipeline, SW128 XOR swizzle, plain ldmatrix both operands.
// grid (16 m-tiles, 16 ab), 512 threads.
// ============================================================
#define BK        64
#define ATILE_B   (128 * 128)       // 16 KB (128 rows x 128B)
#define STAGE_B   (2 * ATILE_B)     // A + B per stage = 32 KB
#define NSTAGES   3
#define NCHUNKS   (NN / BK)         // 32

__global__ void __launch_bounds__(512, 1)
aggregate_mma(const float* __restrict__ bias, float* __restrict__ out) {
    extern __shared__ char smem_raw[];
    const uint32_t sbase = (smem_u32(smem_raw) + 127) & ~127u;

    const int tid  = threadIdx.x;
    const int wid  = tid >> 5;
    const int lane = tid & 31;
    const int warp_m = (wid & 3) * 32;     // 0,32,64,96
    const int warp_d = (wid >> 2) * 32;    // 0,32,64,96
    const int m0   = blockIdx.x * 128;
    const int ab   = blockIdx.y;

    const char* Ag = (const char*)(g_adjT + (size_t)m0 * NN);
    const char* Bg = (const char*)(g_yT + (size_t)ab * DOUT * NN);

    // loader mapping: 512 threads, 2 f4 for A + 2 f4 for B per stage
    const int lrow = tid >> 2;                  // 0..127
    const int lc0  = (tid & 3) * 2;             // 0,2,4,6

    auto load_buf = [&](int buf, int c) {
        const uint32_t Ao = sbase + buf * STAGE_B;
        const uint32_t Bo = Ao + ATILE_B;
        const size_t rowoff = (size_t)lrow * NN + c * BK;
#pragma unroll
        for (int i = 0; i < 2; ++i) {
            int ch = lc0 + i;
            uint32_t sw = (uint32_t)(ch ^ (lrow & 7)) * 16 + (uint32_t)lrow * 128;
            const size_t goff = (rowoff + ch * 8) * 2;
            cp_async16(Ao + sw, Ag + goff);
            cp_async16(Bo + sw, Bg + goff);
        }
        cp_commit();
    };

    float acc[2][4][4];
#pragma unroll
    for (int mf = 0; mf < 2; ++mf)
#pragma unroll
        for (int nf = 0; nf < 4; ++nf)
#pragma unroll
            for (int e = 0; e < 4; ++e) acc[mf][nf][e] = 0.f;

    load_buf(0, 0);
    load_buf(1, 1);

    const int portion = lane >> 3;
    const int w8 = lane & 7;

    for (int c = 0; c < NCHUNKS; ++c) {
        if (c == NCHUNKS - 1) cp_wait<0>(); else cp_wait<1>();
        __syncthreads();
        if (c + 2 < NCHUNKS) load_buf((c + 2) % NSTAGES, c + 2);

        const uint32_t Ao = sbase + (c % NSTAGES) * STAGE_B;
        const uint32_t Bo = Ao + ATILE_B;

#pragma unroll
        for (int ks = 0; ks < 4; ++ks) {
            const int kb8 = ks * 2;
            uint32_t a[2][4], b[4][2];
#pragma unroll
            for (int mf = 0; mf < 2; ++mf) {
                int row = warp_m + mf * 16 + (portion & 1) * 8 + w8;
                int ch  = kb8 + (portion >> 1);
                ldsm_x4(a[mf], Ao + (uint32_t)row * 128 + (uint32_t)(ch ^ (row & 7)) * 16);
            }
#pragma unroll
            for (int nfp = 0; nfp < 2; ++nfp) {
                int row = warp_d + nfp * 16 + (portion >> 1) * 8 + w8;
                int ch  = kb8 + (portion & 1);
                uint32_t r[4];
                ldsm_x4(r, Bo + (uint32_t)row * 128 + (uint32_t)(ch ^ (row & 7)) * 16);
                b[2 * nfp][0]     = r[0];
                b[2 * nfp][1]     = r[1];
                b[2 * nfp + 1][0] = r[2];
                b[2 * nfp + 1][1] = r[3];
            }
#pragma unroll
            for (int mf = 0; mf < 2; ++mf)
#pragma unroll
                for (int nf = 0; nf < 4; ++nf)
                    mma16816(acc[mf][nf], a[mf], b[nf]);
        }
    }

    // epilogue: rinv[m] * acc + bias[d], relu
    const int g  = lane >> 2;
    const int tc = lane & 3;
    float* outab = out + (size_t)ab * NN * DOUT;
#pragma unroll
    for (int mf = 0; mf < 2; ++mf) {
        const int mrow0 = m0 + warp_m + mf * 16 + g;
        const float rv0 = g_rinv[mrow0];
        const float rv1 = g_rinv[mrow0 + 8];
#pragma unroll
        for (int nf = 0; nf < 4; ++nf) {
            const int d0 = warp_d + nf * 8 + tc * 2;
            const float b0 = __ldg(&bias[d0]);
            const float b1 = __ldg(&bias[d0 + 1]);
            float2 v0, v1;
            v0.x = fmaxf(fmaf(acc[mf][nf][0], rv0, b0), 0.f);
            v0.y = fmaxf(fmaf(acc[mf][nf][1], rv0, b1), 0.f);
            v1.x = fmaxf(fmaf(acc[mf][nf][2], rv1, b0), 0.f);
            v1.y = fmaxf(fmaf(acc[mf][nf][3], rv1, b1), 0.f);
            *(float2*)&outab[(size_t)mrow0 * DOUT + d0]       = v0;
            *(float2*)&outab[(size_t)(mrow0 + 8) * DOUT + d0] = v1;
        }
    }
}

// ============================================================
extern "C" void kernel_launch(void* const* d_in, const int* in_sizes, int n_in,
                              void* d_out, int out_size) {
    const float* adj  = (const float*)d_in[0];
    const float* x    = (const float*)d_in[1];
    const float* w    = (const float*)d_in[2];
    const float* bias = (const float*)d_in[3];
    float* out        = (float*)d_out;

    const int agg_smem = NSTAGES * STAGE_B + 256;   // 96 KB + align slack
    cudaFuncSetAttribute(aggregate_mma, cudaFuncAttributeMaxDynamicSharedMemorySize, agg_smem);

    transpose_colsum_kernel<<<dim3(64, 64), dim3(32, 8)>>>(adj);
    rinv_kernel<<<NN / 256, 256>>>();
    project_kernel<<<dim3(16, 16), 256>>>(x, w);
    aggregate_mma<<<dim3(16, 16), 512, agg_smem>>>(bias, out);
}

// round 6
// speedup vs baseline: 4.8830x; 1.1896x over previous
#include <cuda_runtime.h>
#include <cuda_bf16.h>
#include <cstdint>

// dims fixed by setup_inputs
#define NN     2048
#define ABATCH 16
#define DIN    128
#define DOUT   128
#define TCHUNKS 64

// ---------------- device scratch (no allocs allowed) ----------------
__device__ float g_part[TCHUNKS * NN];
__device__ float g_rinv[NN];
__device__ __nv_bfloat16 g_adjT[(size_t)NN * NN];           // adjT[m][n], 8 MB
__device__ __nv_bfloat16 g_yT[(size_t)ABATCH * DOUT * NN];  // yT[ab][d][n], 8 MB
__device__ __nv_bfloat16 g_xb[(size_t)ABATCH * NN * DIN];   // bf16 x, 8 MB
__device__ __nv_bfloat16 g_wt[DOUT * DIN];                  // WT[d][k] bf16

__device__ __forceinline__ uint32_t smem_u32(const void* p) {
    return (uint32_t)__cvta_generic_to_shared(p);
}
__device__ __forceinline__ void cp_async16(uint32_t dst, const void* src) {
    asm volatile("cp.async.cg.shared.global [%0], [%1], 16;" :: "r"(dst), "l"(src));
}
__device__ __forceinline__ void cp_commit() {
    asm volatile("cp.async.commit_group;" ::: "memory");
}
template <int N>
__device__ __forceinline__ void cp_wait() {
    asm volatile("cp.async.wait_group %0;" :: "n"(N) : "memory");
}
__device__ __forceinline__ void ldsm_x4(uint32_t* r, uint32_t addr) {
    asm volatile("ldmatrix.sync.aligned.m8n8.x4.shared.b16 {%0,%1,%2,%3}, [%4];"
                 : "=r"(r[0]), "=r"(r[1]), "=r"(r[2]), "=r"(r[3]) : "r"(addr));
}
__device__ __forceinline__ void mma16816(float* d, const uint32_t* a, const uint32_t* b) {
    asm volatile(
        "mma.sync.aligned.m16n8k16.row.col.f32.bf16.bf16.f32 "
        "{%0,%1,%2,%3}, {%4,%5,%6,%7}, {%8,%9}, {%0,%1,%2,%3};"
        : "+f"(d[0]), "+f"(d[1]), "+f"(d[2]), "+f"(d[3])
        : "r"(a[0]), "r"(a[1]), "r"(a[2]), "r"(a[3]), "r"(b[0]), "r"(b[1]));
}
__device__ __forceinline__ uint32_t pack_bf2(float a, float b) {
    __nv_bfloat162 t = __floats2bfloat162_rn(a, b);
    return *(uint32_t*)&t;
}

// ============================================================
// Kernel 1: fused transpose + partial column sums
// ============================================================
__global__ void transpose_colsum_kernel(const float* __restrict__ adj) {
    __shared__ float t[32][33];
    int mx = blockIdx.x * 32, ny = blockIdx.y * 32;
    int tx = threadIdx.x, ty = threadIdx.y;
    float v[4];
#pragma unroll
    for (int i = 0; i < 4; ++i) {
        v[i] = adj[(size_t)(ny + ty + i * 8) * NN + mx + tx];
        t[ty + i * 8][tx] = v[i];
    }
    __syncthreads();
#pragma unroll
    for (int i = 0; i < 4; ++i)
        g_adjT[(size_t)(mx + ty + i * 8) * NN + ny + tx] = __float2bfloat16(t[tx][ty + i * 8]);
    float s = v[0] + v[1] + v[2] + v[3];
    __syncthreads();
    t[ty][tx] = s;
    __syncthreads();
    if (ty == 0) {
        float tot = 0.f;
#pragma unroll
        for (int r = 0; r < 8; ++r) tot += t[r][tx];
        g_part[blockIdx.y * NN + mx + tx] = tot;
    }
}

// ============================================================
// Kernel 2: reduce -> rinv = rsqrt(colsum)
// ============================================================
__global__ void rinv_kernel() {
    int col = blockIdx.x * 256 + threadIdx.x;
    float s = 0.f;
#pragma unroll
    for (int c = 0; c < TCHUNKS; ++c)
        s += g_part[c * NN + col];
    g_rinv[col] = rsqrtf(s);
}

// ============================================================
// Kernel 2b: convert x -> bf16 (8 elems/thread), and WT[d][k] = bf16(W[k][d])
// ============================================================
__global__ void convx_kernel(const float* __restrict__ x) {
    size_t i = ((size_t)blockIdx.x * 256 + threadIdx.x) * 8;
    float4 v0 = *(const float4*)&x[i];
    float4 v1 = *(const float4*)&x[i + 4];
    uint4 pk;
    pk.x = pack_bf2(v0.x, v0.y);
    pk.y = pack_bf2(v0.z, v0.w);
    pk.z = pack_bf2(v1.x, v1.y);
    pk.w = pack_bf2(v1.z, v1.w);
    *(uint4*)((char*)g_xb + i * 2) = pk;
}
__global__ void convwt_kernel(const float* __restrict__ w) {
    int idx = blockIdx.x * 256 + threadIdx.x;   // 64 blocks x 256 = 16384
    int d = idx >> 7, k = idx & 127;
    g_wt[d * DIN + k] = __float2bfloat16(w[k * DOUT + d]);
}

// ============================================================
// Kernel 3: projection via mma.sync (single-shot, K=128 in 2 chunks of 64)
//   yT[ab][d][n] = bf16( rinv[n] * sum_k WT[d][k] * xb[ab][n][k] )
// A = WT rows (d), B = xb rows (n), both k-contig -> plain ldmatrix.
// CTA: 128d x 128n, 512 threads, 16 warps (4d x 4n), warp tile 32x32.
// grid (16 n-tiles, 16 ab).
// ============================================================
#define PATILE_B (128 * 128)   // one 64-k chunk: 128 rows x 128B = 16 KB

__global__ void __launch_bounds__(512, 1)
project_mma(int dummy) {
    extern __shared__ char smem_raw[];
    const uint32_t sbase = (smem_u32(smem_raw) + 127) & ~127u;
    const uint32_t Ao0 = sbase;                    // WT chunks: 2 x 16KB
    const uint32_t Bo0 = sbase + 2 * PATILE_B;     // xb chunks: 2 x 16KB

    const int tid  = threadIdx.x;
    const int wid  = tid >> 5;
    const int lane = tid & 31;
    const int warp_m = (wid & 3) * 32;     // d
    const int warp_d = (wid >> 2) * 32;    // n (local)
    const int n0 = blockIdx.x * 128;
    const int ab = blockIdx.y;

    const char* Ag = (const char*)g_wt;                                   // [128][128] bf16
    const char* Bg = (const char*)(g_xb + ((size_t)ab * NN + n0) * DIN);  // [128][128] bf16

    // load both 64-k chunks of A and B: per chunk 1024+1024 f4, 4 f4/thread/chunk
    const int lrow = tid >> 2;          // 0..127
    const int lc0  = (tid & 3) * 2;
#pragma unroll
    for (int c = 0; c < 2; ++c) {
#pragma unroll
        for (int i = 0; i < 2; ++i) {
            int ch = lc0 + i;
            uint32_t sw = (uint32_t)(ch ^ (lrow & 7)) * 16 + (uint32_t)lrow * 128;
            size_t goff = ((size_t)lrow * DIN + c * 64 + ch * 8) * 2;
            cp_async16(Ao0 + c * PATILE_B + sw, Ag + goff);
            cp_async16(Bo0 + c * PATILE_B + sw, Bg + goff);
        }
    }
    cp_commit();
    cp_wait<0>();
    __syncthreads();

    float acc[2][4][4];
#pragma unroll
    for (int mf = 0; mf < 2; ++mf)
#pragma unroll
        for (int nf = 0; nf < 4; ++nf)
#pragma unroll
            for (int e = 0; e < 4; ++e) acc[mf][nf][e] = 0.f;

    const int portion = lane >> 3;
    const int w8 = lane & 7;

#pragma unroll
    for (int c = 0; c < 2; ++c) {
        const uint32_t Ao = Ao0 + c * PATILE_B;
        const uint32_t Bo = Bo0 + c * PATILE_B;
#pragma unroll
        for (int ks = 0; ks < 4; ++ks) {
            const int kb8 = ks * 2;
            uint32_t a[2][4], b[4][2];
#pragma unroll
            for (int mf = 0; mf < 2; ++mf) {
                int row = warp_m + mf * 16 + (portion & 1) * 8 + w8;
                int ch  = kb8 + (portion >> 1);
                ldsm_x4(a[mf], Ao + (uint32_t)row * 128 + (uint32_t)(ch ^ (row & 7)) * 16);
            }
#pragma unroll
            for (int nfp = 0; nfp < 2; ++nfp) {
                int row = warp_d + nfp * 16 + (portion >> 1) * 8 + w8;
                int ch  = kb8 + (portion & 1);
                uint32_t r[4];
                ldsm_x4(r, Bo + (uint32_t)row * 128 + (uint32_t)(ch ^ (row & 7)) * 16);
                b[2 * nfp][0]     = r[0];
                b[2 * nfp][1]     = r[1];
                b[2 * nfp + 1][0] = r[2];
                b[2 * nfp + 1][1] = r[3];
            }
#pragma unroll
            for (int mf = 0; mf < 2; ++mf)
#pragma unroll
                for (int nf = 0; nf < 4; ++nf)
                    mma16816(acc[mf][nf], a[mf], b[nf]);
        }
    }

    // epilogue: rows=d, cols=n; scale by rinv[n], store bf16 pairs to yT[ab][d][n]
    const int g  = lane >> 2;
    const int tc = lane & 3;
    char* yT = (char*)(g_yT + (size_t)ab * DOUT * NN);
#pragma unroll
    for (int mf = 0; mf < 2; ++mf) {
        const int d0g = warp_m + mf * 16 + g;
#pragma unroll
        for (int nf = 0; nf < 4; ++nf) {
            const int ng = n0 + warp_d + nf * 8 + tc * 2;
            const float rv0 = g_rinv[ng];
            const float rv1 = g_rinv[ng + 1];
            *(uint32_t*)(yT + ((size_t)d0g * NN + ng) * 2) =
                pack_bf2(acc[mf][nf][0] * rv0, acc[mf][nf][1] * rv1);
            *(uint32_t*)(yT + ((size_t)(d0g + 8) * NN + ng) * 2) =
                pack_bf2(acc[mf][nf][2] * rv0, acc[mf][nf][3] * rv1);
        }
    }
}

// ============================================================
// Kernel 4: mma.sync bf16 aggregate (v3: 4-stage cp.async + k-step frag prefetch)
//   out[ab][m][d] = relu( rinv[m] * sum_n adjT[m][n]*yT[ab][d][n] + bias[d] )
// CTA 128m x 128d, BK=64, 16 warps (4m x 4d), warp 32x32.
// grid (16 m-tiles, 16 ab), 512 threads, 128KB smem.
// ============================================================
#define BK        64
#define ATILE_B   (128 * 128)       // 16 KB
#define STAGE_B   (2 * ATILE_B)     // 32 KB
#define NSTAGES   4
#define NCHUNKS   (NN / BK)         // 32

__global__ void __launch_bounds__(512, 1)
aggregate_mma(const float* __restrict__ bias, float* __restrict__ out) {
    extern __shared__ char smem_raw[];
    const uint32_t sbase = (smem_u32(smem_raw) + 127) & ~127u;

    const int tid  = threadIdx.x;
    const int wid  = tid >> 5;
    const int lane = tid & 31;
    const int warp_m = (wid & 3) * 32;
    const int warp_d = (wid >> 2) * 32;
    const int m0   = blockIdx.x * 128;
    const int ab   = blockIdx.y;

    const char* Ag = (const char*)(g_adjT + (size_t)m0 * NN);
    const char* Bg = (const char*)(g_yT + (size_t)ab * DOUT * NN);

    const int lrow = tid >> 2;
    const int lc0  = (tid & 3) * 2;

    auto load_buf = [&](int buf, int c) {
        const uint32_t Ao = sbase + buf * STAGE_B;
        const uint32_t Bo = Ao + ATILE_B;
        const size_t rowoff = (size_t)lrow * NN + c * BK;
#pragma unroll
        for (int i = 0; i < 2; ++i) {
            int ch = lc0 + i;
            uint32_t sw = (uint32_t)(ch ^ (lrow & 7)) * 16 + (uint32_t)lrow * 128;
            const size_t goff = (rowoff + ch * 8) * 2;
            cp_async16(Ao + sw, Ag + goff);
            cp_async16(Bo + sw, Bg + goff);
        }
        cp_commit();
    };

    float acc[2][4][4];
#pragma unroll
    for (int mf = 0; mf < 2; ++mf)
#pragma unroll
        for (int nf = 0; nf < 4; ++nf)
#pragma unroll
            for (int e = 0; e < 4; ++e) acc[mf][nf][e] = 0.f;

    load_buf(0, 0);
    load_buf(1, 1);
    load_buf(2, 2);

    const int portion = lane >> 3;
    const int w8 = lane & 7;

    uint32_t afr[2][2][4], bfr[2][4][2];

    for (int c = 0; c < NCHUNKS; ++c) {
        if (c + 2 < NCHUNKS)      cp_wait<2>();
        else if (c + 1 < NCHUNKS) cp_wait<1>();
        else                      cp_wait<0>();
        __syncthreads();
        if (c + 3 < NCHUNKS) load_buf((c + 3) & 3, c + 3);

        const uint32_t Ao = sbase + (c & 3) * STAGE_B;
        const uint32_t Bo = Ao + ATILE_B;

        auto ldfrag = [&](int ks, uint32_t (&a)[2][4], uint32_t (&b)[4][2]) {
            const int kb8 = ks * 2;
#pragma unroll
            for (int mf = 0; mf < 2; ++mf) {
                int row = warp_m + mf * 16 + (portion & 1) * 8 + w8;
                int ch  = kb8 + (portion >> 1);
                ldsm_x4(a[mf], Ao + (uint32_t)row * 128 + (uint32_t)(ch ^ (row & 7)) * 16);
            }
#pragma unroll
            for (int nfp = 0; nfp < 2; ++nfp) {
                int row = warp_d + nfp * 16 + (portion >> 1) * 8 + w8;
                int ch  = kb8 + (portion & 1);
                uint32_t r[4];
                ldsm_x4(r, Bo + (uint32_t)row * 128 + (uint32_t)(ch ^ (row & 7)) * 16);
                b[2 * nfp][0]     = r[0];
                b[2 * nfp][1]     = r[1];
                b[2 * nfp + 1][0] = r[2];
                b[2 * nfp + 1][1] = r[3];
            }
        };

        ldfrag(0, afr[0], bfr[0]);
#pragma unroll
        for (int ks = 0; ks < 4; ++ks) {
            const int cur = ks & 1;
            if (ks < 3) ldfrag(ks + 1, afr[cur ^ 1], bfr[cur ^ 1]);
#pragma unroll
            for (int mf = 0; mf < 2; ++mf)
#pragma unroll
                for (int nf = 0; nf < 4; ++nf)
                    mma16816(acc[mf][nf], afr[cur][mf], bfr[cur][nf]);
        }
    }

    // epilogue: rinv[m] * acc + bias[d], relu
    const int g  = lane >> 2;
    const int tc = lane & 3;
    float* outab = out + (size_t)ab * NN * DOUT;
#pragma unroll
    for (int mf = 0; mf < 2; ++mf) {
        const int mrow0 = m0 + warp_m + mf * 16 + g;
        const float rv0 = g_rinv[mrow0];
        const float rv1 = g_rinv[mrow0 + 8];
#pragma unroll
        for (int nf = 0; nf < 4; ++nf) {
            const int d0 = warp_d + nf * 8 + tc * 2;
            const float b0 = __ldg(&bias[d0]);
            const float b1 = __ldg(&bias[d0 + 1]);
            float2 v0, v1;
            v0.x = fmaxf(fmaf(acc[mf][nf][0], rv0, b0), 0.f);
            v0.y = fmaxf(fmaf(acc[mf][nf][1], rv0, b1), 0.f);
            v1.x = fmaxf(fmaf(acc[mf][nf][2], rv1, b0), 0.f);
            v1.y = fmaxf(fmaf(acc[mf][nf][3], rv1, b1), 0.f);
            *(float2*)&outab[(size_t)mrow0 * DOUT + d0]       = v0;
            *(float2*)&outab[(size_t)(mrow0 + 8) * DOUT + d0] = v1;
        }
    }
}

// ============================================================
extern "C" void kernel_launch(void* const* d_in, const int* in_sizes, int n_in,
                              void* d_out, int out_size) {
    const float* adj  = (const float*)d_in[0];
    const float* x    = (const float*)d_in[1];
    const float* w    = (const float*)d_in[2];
    const float* bias = (const float*)d_in[3];
    float* out        = (float*)d_out;

    const int agg_smem  = NSTAGES * STAGE_B + 256;   // 128 KB + slack
    const int proj_smem = 4 * PATILE_B + 256;        // 64 KB + slack
    cudaFuncSetAttribute(aggregate_mma, cudaFuncAttributeMaxDynamicSharedMemorySize, agg_smem);
    cudaFuncSetAttribute(project_mma, cudaFuncAttributeMaxDynamicSharedMemorySize, proj_smem);

    transpose_colsum_kernel<<<dim3(64, 64), dim3(32, 8)>>>(adj);
    rinv_kernel<<<NN / 256, 256>>>();
    convx_kernel<<<(ABATCH * NN * DIN) / (256 * 8), 256>>>(x);
    convwt_kernel<<<64, 256>>>(w);
    project_mma<<<dim3(16, 16), 512, proj_smem>>>(0);
    aggregate_mma<<<dim3(16, 16), 512, agg_smem>>>(bias, out);
}